// round 11
// baseline (speedup 1.0000x reference)
#include <cuda_runtime.h>
#include <cuda_bf16.h>
#include <cstdint>

// BackProjNet: out[65535 - v] = SCALE * sum_{j=0..1023} x[idx[v*1024+j]] * w[v*1024+j] + bias[v]
// Inputs: x (376832 f32), weight (67108864 f32), bias (65536 f32), indices (67108864 i32)
//
// R9 strategy: the 1.47MB sinogram fits EXACTLY in 8 x 184KB of shared memory.
// Launch clusters of 8 CTAs; each CTA stages sino[rank*47104 .. +47104) in its
// smem. Every random gather becomes mapa + ld.shared::cluster (DSMEM), taking
// the 64M 4B random gathers off the L1 sector path (R6's 92.8% ceiling).
// Index/weight streams stay on the global path, now uncontended.

static constexpr int   VOXELS  = 256 * 256;     // 65536
static constexpr int   VE      = 1024;          // views*extent per voxel
static constexpr int   SINO_N  = 376832;        // 512*736
static constexpr int   CLUSTER = 8;
static constexpr int   CHUNK   = SINO_N / CLUSTER;   // 47104 floats = 184 KB
static constexpr float SCALE_F = (float)(3.14159265358979323846 / 1024.0); // 2pi/(2*512*2)

__device__ __forceinline__ float dsmem_gather(uint32_t sbase, uint32_t idx)
{
    const uint32_t rank = idx / (uint32_t)CHUNK;          // 0..7 (magic-mul)
    const uint32_t off  = idx - rank * (uint32_t)CHUNK;
    const uint32_t la   = sbase + off * 4u;
    uint32_t ra;
    asm("mapa.shared::cluster.u32 %0, %1, %2;" : "=r"(ra) : "r"(la), "r"(rank));
    float s;
    asm("ld.shared::cluster.f32 %0, [%1];" : "=f"(s) : "r"(ra));
    return s;
}

__global__ __launch_bounds__(1024, 1) __cluster_dims__(CLUSTER, 1, 1)
void backproj_kernel(const float* __restrict__ sino,
                     const float* __restrict__ weight,
                     const float* __restrict__ bias,
                     const int*   __restrict__ indices,
                     float* __restrict__ out)
{
    extern __shared__ float s_chunk[];

    uint32_t rank;
    asm("mov.u32 %0, %%cluster_ctarank;" : "=r"(rank));

    const int tid  = threadIdx.x;
    const int lane = tid & 31;

    // Stage this CTA's 47104-float chunk of the sinogram (coalesced float4).
    {
        const float4* src = reinterpret_cast<const float4*>(sino) + (size_t)rank * (CHUNK / 4);
        float4*       dst = reinterpret_cast<float4*>(s_chunk);
        for (int i = tid; i < CHUNK / 4; i += 1024)
            dst[i] = src[i];
    }

    uint32_t sbase;
    asm("{ .reg .u64 t; cvta.to.shared.u64 t, %1; cvt.u32.u64 %0, t; }"
        : "=r"(sbase) : "l"(s_chunk));

    // All 8 CTAs must finish staging before anyone gathers.
    asm volatile("barrier.cluster.arrive.aligned;" ::: "memory");
    asm volatile("barrier.cluster.wait.aligned;"   ::: "memory");

    const int totalWarps = gridDim.x * 32;
    const int warpGlobal = blockIdx.x * 32 + (tid >> 5);

    for (int v = warpGlobal; v < VOXELS; v += totalWarps) {
        const long long base = (long long)v * VE;

        float acc = 0.0f;

        #pragma unroll
        for (int k = 0; k < 8; ++k) {
            const long long j = base + (long long)(k * 128 + lane * 4);
            const int4   i4 = __ldcs(reinterpret_cast<const int4*>(indices + j));
            const float4 w4 = __ldcs(reinterpret_cast<const float4*>(weight + j));

            const float s0 = dsmem_gather(sbase, (uint32_t)i4.x);
            const float s1 = dsmem_gather(sbase, (uint32_t)i4.y);
            const float s2 = dsmem_gather(sbase, (uint32_t)i4.z);
            const float s3 = dsmem_gather(sbase, (uint32_t)i4.w);

            acc = fmaf(s0, w4.x, acc);
            acc = fmaf(s1, w4.y, acc);
            acc = fmaf(s2, w4.z, acc);
            acc = fmaf(s3, w4.w, acc);
        }

        #pragma unroll
        for (int o = 16; o > 0; o >>= 1)
            acc += __shfl_xor_sync(0xffffffffu, acc, o);

        if (lane == 0)
            out[VOXELS - 1 - v] = acc * SCALE_F + bias[v];
    }

    // No CTA may exit while cluster peers can still read its smem.
    asm volatile("barrier.cluster.arrive.aligned;" ::: "memory");
    asm volatile("barrier.cluster.wait.aligned;"   ::: "memory");
}

extern "C" void kernel_launch(void* const* d_in, const int* in_sizes, int n_in,
                              void* d_out, int out_size)
{
    const float* x       = (const float*)d_in[0];
    const float* weight  = (const float*)d_in[1];
    const float* bias    = (const float*)d_in[2];
    const int*   indices = (const int*)d_in[3];
    float*       out     = (float*)d_out;

    const int smemBytes = CHUNK * (int)sizeof(float);   // 188416 B = 184 KB

    cudaFuncSetAttribute(backproj_kernel,
                         cudaFuncAttributeMaxDynamicSharedMemorySize, smemBytes);

    // 18 clusters x 8 CTAs = 144 CTAs; same-die placement gives 9 clusters/die
    // (74 SMs/die), all resident in one wave. Grid-stride covers all voxels.
    backproj_kernel<<<144, 1024, smemBytes>>>(x, weight, bias, indices, out);
}

// round 12
// speedup vs baseline: 1.0008x; 1.0008x over previous
#include <cuda_runtime.h>
#include <cuda_bf16.h>
#include <cstdint>

// BackProjNet: out[65535 - v] = SCALE * sum_{j=0..1023} x[idx[v*1024+j]] * w[v*1024+j] + bias[v]
// Inputs: x (376832 f32), weight (67108864 f32), bias (65536 f32), indices (67108864 i32)
//
// R9 strategy: the 1.47MB sinogram fits EXACTLY in 8 x 184KB of shared memory.
// Launch clusters of 8 CTAs; each CTA stages sino[rank*47104 .. +47104) in its
// smem. Every random gather becomes mapa + ld.shared::cluster (DSMEM), taking
// the 64M 4B random gathers off the L1 sector path (R6's 92.8% ceiling).
// Index/weight streams stay on the global path, now uncontended.

static constexpr int   VOXELS  = 256 * 256;     // 65536
static constexpr int   VE      = 1024;          // views*extent per voxel
static constexpr int   SINO_N  = 376832;        // 512*736
static constexpr int   CLUSTER = 8;
static constexpr int   CHUNK   = SINO_N / CLUSTER;   // 47104 floats = 184 KB
static constexpr float SCALE_F = (float)(3.14159265358979323846 / 1024.0); // 2pi/(2*512*2)

__device__ __forceinline__ float dsmem_gather(uint32_t sbase, uint32_t idx)
{
    const uint32_t rank = idx / (uint32_t)CHUNK;          // 0..7 (magic-mul)
    const uint32_t off  = idx - rank * (uint32_t)CHUNK;
    const uint32_t la   = sbase + off * 4u;
    uint32_t ra;
    asm("mapa.shared::cluster.u32 %0, %1, %2;" : "=r"(ra) : "r"(la), "r"(rank));
    float s;
    asm("ld.shared::cluster.f32 %0, [%1];" : "=f"(s) : "r"(ra));
    return s;
}

__global__ __launch_bounds__(1024, 1) __cluster_dims__(CLUSTER, 1, 1)
void backproj_kernel(const float* __restrict__ sino,
                     const float* __restrict__ weight,
                     const float* __restrict__ bias,
                     const int*   __restrict__ indices,
                     float* __restrict__ out)
{
    extern __shared__ float s_chunk[];

    uint32_t rank;
    asm("mov.u32 %0, %%cluster_ctarank;" : "=r"(rank));

    const int tid  = threadIdx.x;
    const int lane = tid & 31;

    // Stage this CTA's 47104-float chunk of the sinogram (coalesced float4).
    {
        const float4* src = reinterpret_cast<const float4*>(sino) + (size_t)rank * (CHUNK / 4);
        float4*       dst = reinterpret_cast<float4*>(s_chunk);
        for (int i = tid; i < CHUNK / 4; i += 1024)
            dst[i] = src[i];
    }

    uint32_t sbase;
    asm("{ .reg .u64 t; cvta.to.shared.u64 t, %1; cvt.u32.u64 %0, t; }"
        : "=r"(sbase) : "l"(s_chunk));

    // All 8 CTAs must finish staging before anyone gathers.
    asm volatile("barrier.cluster.arrive.aligned;" ::: "memory");
    asm volatile("barrier.cluster.wait.aligned;"   ::: "memory");

    const int totalWarps = gridDim.x * 32;
    const int warpGlobal = blockIdx.x * 32 + (tid >> 5);

    for (int v = warpGlobal; v < VOXELS; v += totalWarps) {
        const long long base = (long long)v * VE;

        float acc = 0.0f;

        #pragma unroll
        for (int k = 0; k < 8; ++k) {
            const long long j = base + (long long)(k * 128 + lane * 4);
            const int4   i4 = __ldcs(reinterpret_cast<const int4*>(indices + j));
            const float4 w4 = __ldcs(reinterpret_cast<const float4*>(weight + j));

            const float s0 = dsmem_gather(sbase, (uint32_t)i4.x);
            const float s1 = dsmem_gather(sbase, (uint32_t)i4.y);
            const float s2 = dsmem_gather(sbase, (uint32_t)i4.z);
            const float s3 = dsmem_gather(sbase, (uint32_t)i4.w);

            acc = fmaf(s0, w4.x, acc);
            acc = fmaf(s1, w4.y, acc);
            acc = fmaf(s2, w4.z, acc);
            acc = fmaf(s3, w4.w, acc);
        }

        #pragma unroll
        for (int o = 16; o > 0; o >>= 1)
            acc += __shfl_xor_sync(0xffffffffu, acc, o);

        if (lane == 0)
            out[VOXELS - 1 - v] = acc * SCALE_F + bias[v];
    }

    // No CTA may exit while cluster peers can still read its smem.
    asm volatile("barrier.cluster.arrive.aligned;" ::: "memory");
    asm volatile("barrier.cluster.wait.aligned;"   ::: "memory");
}

extern "C" void kernel_launch(void* const* d_in, const int* in_sizes, int n_in,
                              void* d_out, int out_size)
{
    const float* x       = (const float*)d_in[0];
    const float* weight  = (const float*)d_in[1];
    const float* bias    = (const float*)d_in[2];
    const int*   indices = (const int*)d_in[3];
    float*       out     = (float*)d_out;

    const int smemBytes = CHUNK * (int)sizeof(float);   // 188416 B = 184 KB

    cudaFuncSetAttribute(backproj_kernel,
                         cudaFuncAttributeMaxDynamicSharedMemorySize, smemBytes);

    // 18 clusters x 8 CTAs = 144 CTAs; same-die placement gives 9 clusters/die
    // (74 SMs/die), all resident in one wave. Grid-stride covers all voxels.
    backproj_kernel<<<144, 1024, smemBytes>>>(x, weight, bias, indices, out);
}

// round 13
// speedup vs baseline: 1.0011x; 1.0003x over previous
#include <cuda_runtime.h>
#include <cuda_bf16.h>
#include <cstdint>

// BackProjNet: out[65535 - v] = SCALE * sum_{j=0..1023} x[idx[v*1024+j]] * w[v*1024+j] + bias[v]
// Inputs: x (376832 f32), weight (67108864 f32), bias (65536 f32), indices (67108864 i32)
//
// R9 strategy: the 1.47MB sinogram fits EXACTLY in 8 x 184KB of shared memory.
// Launch clusters of 8 CTAs; each CTA stages sino[rank*47104 .. +47104) in its
// smem. Every random gather becomes mapa + ld.shared::cluster (DSMEM), taking
// the 64M 4B random gathers off the L1 sector path (R6's 92.8% ceiling).
// Index/weight streams stay on the global path, now uncontended.

static constexpr int   VOXELS  = 256 * 256;     // 65536
static constexpr int   VE      = 1024;          // views*extent per voxel
static constexpr int   SINO_N  = 376832;        // 512*736
static constexpr int   CLUSTER = 8;
static constexpr int   CHUNK   = SINO_N / CLUSTER;   // 47104 floats = 184 KB
static constexpr float SCALE_F = (float)(3.14159265358979323846 / 1024.0); // 2pi/(2*512*2)

__device__ __forceinline__ float dsmem_gather(uint32_t sbase, uint32_t idx)
{
    const uint32_t rank = idx / (uint32_t)CHUNK;          // 0..7 (magic-mul)
    const uint32_t off  = idx - rank * (uint32_t)CHUNK;
    const uint32_t la   = sbase + off * 4u;
    uint32_t ra;
    asm("mapa.shared::cluster.u32 %0, %1, %2;" : "=r"(ra) : "r"(la), "r"(rank));
    float s;
    asm("ld.shared::cluster.f32 %0, [%1];" : "=f"(s) : "r"(ra));
    return s;
}

__global__ __launch_bounds__(1024, 1) __cluster_dims__(CLUSTER, 1, 1)
void backproj_kernel(const float* __restrict__ sino,
                     const float* __restrict__ weight,
                     const float* __restrict__ bias,
                     const int*   __restrict__ indices,
                     float* __restrict__ out)
{
    extern __shared__ float s_chunk[];

    uint32_t rank;
    asm("mov.u32 %0, %%cluster_ctarank;" : "=r"(rank));

    const int tid  = threadIdx.x;
    const int lane = tid & 31;

    // Stage this CTA's 47104-float chunk of the sinogram (coalesced float4).
    {
        const float4* src = reinterpret_cast<const float4*>(sino) + (size_t)rank * (CHUNK / 4);
        float4*       dst = reinterpret_cast<float4*>(s_chunk);
        for (int i = tid; i < CHUNK / 4; i += 1024)
            dst[i] = src[i];
    }

    uint32_t sbase;
    asm("{ .reg .u64 t; cvta.to.shared.u64 t, %1; cvt.u32.u64 %0, t; }"
        : "=r"(sbase) : "l"(s_chunk));

    // All 8 CTAs must finish staging before anyone gathers.
    asm volatile("barrier.cluster.arrive.aligned;" ::: "memory");
    asm volatile("barrier.cluster.wait.aligned;"   ::: "memory");

    const int totalWarps = gridDim.x * 32;
    const int warpGlobal = blockIdx.x * 32 + (tid >> 5);

    for (int v = warpGlobal; v < VOXELS; v += totalWarps) {
        const long long base = (long long)v * VE;

        float acc = 0.0f;

        #pragma unroll
        for (int k = 0; k < 8; ++k) {
            const long long j = base + (long long)(k * 128 + lane * 4);
            const int4   i4 = __ldcs(reinterpret_cast<const int4*>(indices + j));
            const float4 w4 = __ldcs(reinterpret_cast<const float4*>(weight + j));

            const float s0 = dsmem_gather(sbase, (uint32_t)i4.x);
            const float s1 = dsmem_gather(sbase, (uint32_t)i4.y);
            const float s2 = dsmem_gather(sbase, (uint32_t)i4.z);
            const float s3 = dsmem_gather(sbase, (uint32_t)i4.w);

            acc = fmaf(s0, w4.x, acc);
            acc = fmaf(s1, w4.y, acc);
            acc = fmaf(s2, w4.z, acc);
            acc = fmaf(s3, w4.w, acc);
        }

        #pragma unroll
        for (int o = 16; o > 0; o >>= 1)
            acc += __shfl_xor_sync(0xffffffffu, acc, o);

        if (lane == 0)
            out[VOXELS - 1 - v] = acc * SCALE_F + bias[v];
    }

    // No CTA may exit while cluster peers can still read its smem.
    asm volatile("barrier.cluster.arrive.aligned;" ::: "memory");
    asm volatile("barrier.cluster.wait.aligned;"   ::: "memory");
}

extern "C" void kernel_launch(void* const* d_in, const int* in_sizes, int n_in,
                              void* d_out, int out_size)
{
    const float* x       = (const float*)d_in[0];
    const float* weight  = (const float*)d_in[1];
    const float* bias    = (const float*)d_in[2];
    const int*   indices = (const int*)d_in[3];
    float*       out     = (float*)d_out;

    const int smemBytes = CHUNK * (int)sizeof(float);   // 188416 B = 184 KB

    cudaFuncSetAttribute(backproj_kernel,
                         cudaFuncAttributeMaxDynamicSharedMemorySize, smemBytes);

    // 18 clusters x 8 CTAs = 144 CTAs; same-die placement gives 9 clusters/die
    // (74 SMs/die), all resident in one wave. Grid-stride covers all voxels.
    backproj_kernel<<<144, 1024, smemBytes>>>(x, weight, bias, indices, out);
}

// round 14
// speedup vs baseline: 1.0015x; 1.0003x over previous
#include <cuda_runtime.h>
#include <cuda_bf16.h>
#include <cstdint>

// BackProjNet: out[65535 - v] = SCALE * sum_{j=0..1023} x[idx[v*1024+j]] * w[v*1024+j] + bias[v]
// Inputs: x (376832 f32), weight (67108864 f32), bias (65536 f32), indices (67108864 i32)
//
// R9 strategy: the 1.47MB sinogram fits EXACTLY in 8 x 184KB of shared memory.
// Launch clusters of 8 CTAs; each CTA stages sino[rank*47104 .. +47104) in its
// smem. Every random gather becomes mapa + ld.shared::cluster (DSMEM), taking
// the 64M 4B random gathers off the L1 sector path (R6's 92.8% ceiling).
// Index/weight streams stay on the global path, now uncontended.

static constexpr int   VOXELS  = 256 * 256;     // 65536
static constexpr int   VE      = 1024;          // views*extent per voxel
static constexpr int   SINO_N  = 376832;        // 512*736
static constexpr int   CLUSTER = 8;
static constexpr int   CHUNK   = SINO_N / CLUSTER;   // 47104 floats = 184 KB
static constexpr float SCALE_F = (float)(3.14159265358979323846 / 1024.0); // 2pi/(2*512*2)

__device__ __forceinline__ float dsmem_gather(uint32_t sbase, uint32_t idx)
{
    const uint32_t rank = idx / (uint32_t)CHUNK;          // 0..7 (magic-mul)
    const uint32_t off  = idx - rank * (uint32_t)CHUNK;
    const uint32_t la   = sbase + off * 4u;
    uint32_t ra;
    asm("mapa.shared::cluster.u32 %0, %1, %2;" : "=r"(ra) : "r"(la), "r"(rank));
    float s;
    asm("ld.shared::cluster.f32 %0, [%1];" : "=f"(s) : "r"(ra));
    return s;
}

__global__ __launch_bounds__(1024, 1) __cluster_dims__(CLUSTER, 1, 1)
void backproj_kernel(const float* __restrict__ sino,
                     const float* __restrict__ weight,
                     const float* __restrict__ bias,
                     const int*   __restrict__ indices,
                     float* __restrict__ out)
{
    extern __shared__ float s_chunk[];

    uint32_t rank;
    asm("mov.u32 %0, %%cluster_ctarank;" : "=r"(rank));

    const int tid  = threadIdx.x;
    const int lane = tid & 31;

    // Stage this CTA's 47104-float chunk of the sinogram (coalesced float4).
    {
        const float4* src = reinterpret_cast<const float4*>(sino) + (size_t)rank * (CHUNK / 4);
        float4*       dst = reinterpret_cast<float4*>(s_chunk);
        for (int i = tid; i < CHUNK / 4; i += 1024)
            dst[i] = src[i];
    }

    uint32_t sbase;
    asm("{ .reg .u64 t; cvta.to.shared.u64 t, %1; cvt.u32.u64 %0, t; }"
        : "=r"(sbase) : "l"(s_chunk));

    // All 8 CTAs must finish staging before anyone gathers.
    asm volatile("barrier.cluster.arrive.aligned;" ::: "memory");
    asm volatile("barrier.cluster.wait.aligned;"   ::: "memory");

    const int totalWarps = gridDim.x * 32;
    const int warpGlobal = blockIdx.x * 32 + (tid >> 5);

    for (int v = warpGlobal; v < VOXELS; v += totalWarps) {
        const long long base = (long long)v * VE;

        float acc = 0.0f;

        #pragma unroll
        for (int k = 0; k < 8; ++k) {
            const long long j = base + (long long)(k * 128 + lane * 4);
            const int4   i4 = __ldcs(reinterpret_cast<const int4*>(indices + j));
            const float4 w4 = __ldcs(reinterpret_cast<const float4*>(weight + j));

            const float s0 = dsmem_gather(sbase, (uint32_t)i4.x);
            const float s1 = dsmem_gather(sbase, (uint32_t)i4.y);
            const float s2 = dsmem_gather(sbase, (uint32_t)i4.z);
            const float s3 = dsmem_gather(sbase, (uint32_t)i4.w);

            acc = fmaf(s0, w4.x, acc);
            acc = fmaf(s1, w4.y, acc);
            acc = fmaf(s2, w4.z, acc);
            acc = fmaf(s3, w4.w, acc);
        }

        #pragma unroll
        for (int o = 16; o > 0; o >>= 1)
            acc += __shfl_xor_sync(0xffffffffu, acc, o);

        if (lane == 0)
            out[VOXELS - 1 - v] = acc * SCALE_F + bias[v];
    }

    // No CTA may exit while cluster peers can still read its smem.
    asm volatile("barrier.cluster.arrive.aligned;" ::: "memory");
    asm volatile("barrier.cluster.wait.aligned;"   ::: "memory");
}

extern "C" void kernel_launch(void* const* d_in, const int* in_sizes, int n_in,
                              void* d_out, int out_size)
{
    const float* x       = (const float*)d_in[0];
    const float* weight  = (const float*)d_in[1];
    const float* bias    = (const float*)d_in[2];
    const int*   indices = (const int*)d_in[3];
    float*       out     = (float*)d_out;

    const int smemBytes = CHUNK * (int)sizeof(float);   // 188416 B = 184 KB

    cudaFuncSetAttribute(backproj_kernel,
                         cudaFuncAttributeMaxDynamicSharedMemorySize, smemBytes);

    // 18 clusters x 8 CTAs = 144 CTAs; same-die placement gives 9 clusters/die
    // (74 SMs/die), all resident in one wave. Grid-stride covers all voxels.
    backproj_kernel<<<144, 1024, smemBytes>>>(x, weight, bias, indices, out);
}

// round 15
// speedup vs baseline: 5.2972x; 5.2894x over previous
#include <cuda_runtime.h>
#include <cuda_bf16.h>
#include <cstdint>

// BackProjNet: out[65535 - v] = SCALE * sum_{j=0..1023} x[idx[v*1024+j]] * w[v*1024+j] + bias[v]
// Inputs: x (376832 f32), weight (67108864 f32), bias (65536 f32), indices (67108864 i32)
// Output: 65536 f32 (flip over both axes of 256x256 == reversed flat index).
//
// Design (R6 lineage — the empirically best structure):
//   warp-per-voxel, 8 warps/CTA, 8192 CTAs, occ ~92%.
//   The kernel is bound by the L1tex wavefront pipe (~32 wavefronts per random
//   32-lane gather; ceiling ~209us). This round: cache-policy tuning only.
//   - streams (indices/weights): __ldcs  -> evict-first, keep L1 for sino
//   - gathers (sino):            ld.global.nc.L1::evict_last -> pin sino in L1,
//     raising L1 hit rate and relieving L2 (82.7% in R6).

static constexpr int   VOXELS  = 256 * 256;   // 65536
static constexpr int   VE      = 1024;        // views * extent per voxel
static constexpr float SCALE_F = (float)(3.14159265358979323846 / 1024.0); // 2pi/(2*512*2)

__device__ __forceinline__ float gather_evict_last(const float* __restrict__ p)
{
    float v;
    asm volatile("ld.global.nc.L1::evict_last.f32 %0, [%1];" : "=f"(v) : "l"(p));
    return v;
}

__global__ __launch_bounds__(256)
void backproj_kernel(const float* __restrict__ sino,
                     const float* __restrict__ weight,
                     const float* __restrict__ bias,
                     const int*   __restrict__ indices,
                     float* __restrict__ out)
{
    const int warp = (int)((blockIdx.x * blockDim.x + threadIdx.x) >> 5);
    const int lane = threadIdx.x & 31;
    if (warp >= VOXELS) return;

    // All offsets fit comfortably in 32 bits (max 2^26).
    const int base = warp * VE + lane * 4;

    float acc = 0.0f;

    // 8 iterations: each lane handles 4 adjacent (index, weight) pairs via
    // int4 + float4 evict-first loads. Per warp-iteration: 128 contiguous
    // pairs -> 512B idx + 512B w, fully coalesced. Full unroll for MLP.
    #pragma unroll
    for (int k = 0; k < 8; ++k) {
        const int j = base + k * 128;
        const int4   i4 = __ldcs(reinterpret_cast<const int4*>(indices + j));
        const float4 w4 = __ldcs(reinterpret_cast<const float4*>(weight + j));

        const float s0 = gather_evict_last(sino + i4.x);
        const float s1 = gather_evict_last(sino + i4.y);
        const float s2 = gather_evict_last(sino + i4.z);
        const float s3 = gather_evict_last(sino + i4.w);

        acc = fmaf(s0, w4.x, acc);
        acc = fmaf(s1, w4.y, acc);
        acc = fmaf(s2, w4.z, acc);
        acc = fmaf(s3, w4.w, acc);
    }

    // Warp tree reduction.
    #pragma unroll
    for (int o = 16; o > 0; o >>= 1)
        acc += __shfl_xor_sync(0xffffffffu, acc, o);

    if (lane == 0)
        out[VOXELS - 1 - warp] = acc * SCALE_F + bias[warp];
}

extern "C" void kernel_launch(void* const* d_in, const int* in_sizes, int n_in,
                              void* d_out, int out_size)
{
    const float* x       = (const float*)d_in[0];
    const float* weight  = (const float*)d_in[1];
    const float* bias    = (const float*)d_in[2];
    const int*   indices = (const int*)d_in[3];
    float*       out     = (float*)d_out;

    // 65536 warps, 8 warps per block -> 8192 blocks of 256 threads.
    backproj_kernel<<<8192, 256>>>(x, weight, bias, indices, out);
}

// round 17
// speedup vs baseline: 5.3002x; 1.0006x over previous
#include <cuda_runtime.h>
#include <cuda_bf16.h>
#include <cstdint>

// BackProjNet: out[65535 - v] = SCALE * sum_{j=0..1023} x[idx[v*1024+j]] * w[v*1024+j] + bias[v]
// Inputs: x (376832 f32), weight (67108864 f32), bias (65536 f32), indices (67108864 i32)
// Output: 65536 f32 (flip over both axes of 256x256 == reversed flat index).
//
// Design (R6 lineage — the empirically best structure):
//   warp-per-voxel, 8 warps/CTA, 8192 CTAs, occ ~92%.
//   The kernel is bound by the L1tex wavefront pipe (~32 wavefronts per random
//   32-lane gather; ceiling ~209us). This round: cache-policy tuning only.
//   - streams (indices/weights): __ldcs  -> evict-first, keep L1 for sino
//   - gathers (sino):            ld.global.nc.L1::evict_last -> pin sino in L1,
//     raising L1 hit rate and relieving L2 (82.7% in R6).

static constexpr int   VOXELS  = 256 * 256;   // 65536
static constexpr int   VE      = 1024;        // views * extent per voxel
static constexpr float SCALE_F = (float)(3.14159265358979323846 / 1024.0); // 2pi/(2*512*2)

__device__ __forceinline__ float gather_evict_last(const float* __restrict__ p)
{
    float v;
    asm volatile("ld.global.nc.L1::evict_last.f32 %0, [%1];" : "=f"(v) : "l"(p));
    return v;
}

__global__ __launch_bounds__(256)
void backproj_kernel(const float* __restrict__ sino,
                     const float* __restrict__ weight,
                     const float* __restrict__ bias,
                     const int*   __restrict__ indices,
                     float* __restrict__ out)
{
    const int warp = (int)((blockIdx.x * blockDim.x + threadIdx.x) >> 5);
    const int lane = threadIdx.x & 31;
    if (warp >= VOXELS) return;

    // All offsets fit comfortably in 32 bits (max 2^26).
    const int base = warp * VE + lane * 4;

    float acc = 0.0f;

    // 8 iterations: each lane handles 4 adjacent (index, weight) pairs via
    // int4 + float4 evict-first loads. Per warp-iteration: 128 contiguous
    // pairs -> 512B idx + 512B w, fully coalesced. Full unroll for MLP.
    #pragma unroll
    for (int k = 0; k < 8; ++k) {
        const int j = base + k * 128;
        const int4   i4 = __ldcs(reinterpret_cast<const int4*>(indices + j));
        const float4 w4 = __ldcs(reinterpret_cast<const float4*>(weight + j));

        const float s0 = gather_evict_last(sino + i4.x);
        const float s1 = gather_evict_last(sino + i4.y);
        const float s2 = gather_evict_last(sino + i4.z);
        const float s3 = gather_evict_last(sino + i4.w);

        acc = fmaf(s0, w4.x, acc);
        acc = fmaf(s1, w4.y, acc);
        acc = fmaf(s2, w4.z, acc);
        acc = fmaf(s3, w4.w, acc);
    }

    // Warp tree reduction.
    #pragma unroll
    for (int o = 16; o > 0; o >>= 1)
        acc += __shfl_xor_sync(0xffffffffu, acc, o);

    if (lane == 0)
        out[VOXELS - 1 - warp] = acc * SCALE_F + bias[warp];
}

extern "C" void kernel_launch(void* const* d_in, const int* in_sizes, int n_in,
                              void* d_out, int out_size)
{
    const float* x       = (const float*)d_in[0];
    const float* weight  = (const float*)d_in[1];
    const float* bias    = (const float*)d_in[2];
    const int*   indices = (const int*)d_in[3];
    float*       out     = (float*)d_out;

    // 65536 warps, 8 warps per block -> 8192 blocks of 256 threads.
    backproj_kernel<<<8192, 256>>>(x, weight, bias, indices, out);
}